// round 9
// baseline (speedup 1.0000x reference)
#include <cuda_runtime.h>
#include <math.h>

#define NNODES 2000
#define NEDGES 8000
#define BB     16
#define TT     512
#define NVV    7
#define LL     64
#define DM     128
#define DLLM   768
#define STOK   1000
#define BNQ    (BB*NVV)   /* 112 */
#define TS2    25         /* attention key tile */
#define SPLITS 4          /* attention S splits */
#define KSEG   6          /* KV gemm K segments */

typedef unsigned long long u64t;

// ---------------- f32x2 packed helpers (sm_100+) ----------------------------
__device__ __forceinline__ u64t f2fma(u64t a, u64t b, u64t c) {
    u64t d; asm("fma.rn.f32x2 %0,%1,%2,%3;" : "=l"(d) : "l"(a), "l"(b), "l"(c)); return d;
}
__device__ __forceinline__ u64t f2mul(u64t a, u64t b) {
    u64t d; asm("mul.rn.f32x2 %0,%1,%2;" : "=l"(d) : "l"(a), "l"(b)); return d;
}
__device__ __forceinline__ u64t f2pack(float lo, float hi) {
    u64t d; asm("mov.b64 %0,{%1,%2};" : "=l"(d) : "f"(lo), "f"(hi)); return d;
}
__device__ __forceinline__ float2 f2unpack(u64t v) {
    float lo, hi; asm("mov.b64 {%0,%1},%2;" : "=f"(lo), "=f"(hi) : "l"(v));
    return make_float2(lo, hi);
}

// ---------------- fast 2^y on FMA/ALU pipes (no MUFU) ------------------------
__device__ __forceinline__ float fexp2(float y) {
    y = fmaxf(y, -120.f);
    float r = y + 12582912.f;            // 1.5*2^23 round trick
    float t = r - 12582912.f;
    float f = y - t;                     // frac in [-0.5, 0.5]
    float p = 1.3333558e-3f;
    p = fmaf(p, f, 9.6181291e-3f);
    p = fmaf(p, f, 5.5504109e-2f);
    p = fmaf(p, f, 2.4022651e-1f);
    p = fmaf(p, f, 6.9314718e-1f);
    p = fmaf(p, f, 1.0f);
    return __int_as_float(__float_as_int(p) + (__float_as_int(r) << 23));
}
#define LOG2E 1.4426950408889634f

// ---------------- scratch (device globals) ----------------------------------
__device__ float g_gemb[BB*DLLM];
__device__ __align__(16) float g_enc [BNQ*LL*DM];
__device__ __align__(16) float g_Qb  [BNQ*LL*DM];
__device__ __align__(16) float g_Kb  [STOK*DM];
__device__ __align__(16) float g_Vb  [STOK*DM];
__device__ __align__(16) float g_rep [BNQ*LL*DM];
__device__ __align__(16) float g_kvp [KSEG*2][STOK*DM];         // KV split-K partials
__device__ __align__(16) float g_accP[SPLITS][BNQ*LL*DM];       // attention partials
__device__ float g_lP[SPLITS][BNQ*LL*8];

// ============================================================================
// Kernel A: fused GAT (blocks 0..15) + normalize/patch/conv (blocks 16..43)
// ============================================================================
__global__ void __launch_bounds__(512) kA_gat_normconv(
        const float* __restrict__ node_input,
        const float* __restrict__ gat_W,
        const float* __restrict__ a_src,
        const float* __restrict__ a_dst,
        const float* __restrict__ gat_bias,
        const int*   __restrict__ edges,
        const float* __restrict__ x_enc,
        const float* __restrict__ conv_W) {
    int tid = threadIdx.x;
    if (blockIdx.x < BB) {
        // ---------------- GAT ----------------
        __shared__ float s_ssrc[NNODES];
        __shared__ float s_sdst[NNODES];
        __shared__ float s_den [NNODES];
        __shared__ float s_wn  [NNODES];
        __shared__ float red[512];
        __shared__ float s_wa[6];
        __shared__ int   s_e64;
        __shared__ float ys[3];
        int b = blockIdx.x;

        for (int idx = 0; idx < 6; ++idx) {
            int which = idx / 3, c = idx % 3;
            const float* a = which ? a_dst : a_src;
            float s = 0.f;
            for (int d = tid; d < DLLM; d += 512) s += gat_W[c*DLLM + d] * a[d];
            red[tid] = s; __syncthreads();
            for (int o = 256; o > 0; o >>= 1) { if (tid < o) red[tid] += red[tid+o]; __syncthreads(); }
            if (tid == 0) s_wa[idx] = red[0];
            __syncthreads();
        }
        if (tid == 0) {
            int all0 = 1;
            for (int i = 1; i < 128; i += 2) if (edges[i] != 0) { all0 = 0; break; }
            s_e64 = all0;
        }
        __syncthreads();
        int e64 = s_e64;
        float wa0=s_wa[0], wa1=s_wa[1], wa2=s_wa[2], wa3=s_wa[3], wa4=s_wa[4], wa5=s_wa[5];

        for (int n = tid; n < NNODES; n += 512) {
            const float* x = node_input + (b*NNODES + n)*3;
            float x0 = x[0], x1 = x[1], x2 = x[2];
            s_ssrc[n] = x0*wa0 + x1*wa1 + x2*wa2;
            s_sdst[n] = x0*wa3 + x1*wa4 + x2*wa5;
            s_den[n] = 0.f; s_wn[n] = 0.f;
        }
        __syncthreads();

        for (int e = tid; e < NEDGES; e += 512) {
            int src, dst;
            if (e64) { const long long* p = (const long long*)edges; src = (int)p[e]; dst = (int)p[NEDGES + e]; }
            else     { src = edges[e]; dst = edges[NEDGES + e]; }
            float lg = s_ssrc[src] + s_sdst[dst];
            lg = lg > 0.f ? lg : 0.2f*lg;
            atomicAdd(&s_den[dst], fexp2(lg * LOG2E));
        }
        __syncthreads();

        for (int e = tid; e < NEDGES; e += 512) {
            int src, dst;
            if (e64) { const long long* p = (const long long*)edges; src = (int)p[e]; dst = (int)p[NEDGES + e]; }
            else     { src = edges[e]; dst = edges[NEDGES + e]; }
            float lg = s_ssrc[src] + s_sdst[dst];
            lg = lg > 0.f ? lg : 0.2f*lg;
            float alpha = fexp2(lg * LOG2E) / (s_den[dst] + 1e-16f);
            atomicAdd(&s_wn[src], alpha);
        }
        __syncthreads();

        for (int c = 0; c < 3; ++c) {
            float s = 0.f;
            for (int n = tid; n < NNODES; n += 512)
                s += s_wn[n] * node_input[(b*NNODES + n)*3 + c];
            red[tid] = s; __syncthreads();
            for (int o = 256; o > 0; o >>= 1) { if (tid < o) red[tid] += red[tid+o]; __syncthreads(); }
            if (tid == 0) ys[c] = red[0];
            __syncthreads();
        }
        for (int d = tid; d < DLLM; d += 512)
            g_gemb[b*DLLM + d] = (ys[0]*gat_W[d] + ys[1]*gat_W[DLLM + d] + ys[2]*gat_W[2*DLLM + d])
                                 * (1.0f/(float)NNODES) + gat_bias[d];
    } else {
        // ---------------- normalize + patch + conv (4 series per block) -----
        __shared__ float xs  [4][TT];
        __shared__ float nred[4][128];
        __shared__ float nst [4][2];
        int g = tid >> 7, o = tid & 127;
        int bn = (blockIdx.x - BB)*4 + g;
        int b = bn / NVV, v = bn % NVV;

        float loc[4];
#pragma unroll
        for (int i = 0; i < 4; ++i) loc[i] = x_enc[(b*TT + o + i*128)*NVV + v];
        float s = loc[0] + loc[1] + loc[2] + loc[3];
        nred[g][o] = s; __syncthreads();
        for (int w = 64; w > 0; w >>= 1) { if (o < w) nred[g][o] += nred[g][o+w]; __syncthreads(); }
        if (o == 0) nst[g][0] = nred[g][0] * (1.0f/TT);
        __syncthreads();
        float mean = nst[g][0];
        float vv = 0.f;
#pragma unroll
        for (int i = 0; i < 4; ++i) { float d = loc[i] - mean; vv += d*d; }
        nred[g][o] = vv; __syncthreads();
        for (int w = 64; w > 0; w >>= 1) { if (o < w) nred[g][o] += nred[g][o+w]; __syncthreads(); }
        if (o == 0) nst[g][1] = rsqrtf(nred[g][0] * (1.0f/TT) + 1e-5f);
        __syncthreads();
        float rstd = nst[g][1];
#pragma unroll
        for (int i = 0; i < 4; ++i) xs[g][o + i*128] = (loc[i] - mean) * rstd;

        float w[48];
#pragma unroll
        for (int j = 0; j < 48; ++j) w[j] = conv_W[o*48 + j];
        __syncthreads();

        for (int l = 0; l < LL; ++l) {
            float sum = 0.f;
#pragma unroll
            for (int k = 0; k < 3; ++k) {
                int j = (l + k + LL - 1) & (LL - 1);
                int base = j * 8;
#pragma unroll
                for (int i = 0; i < 16; ++i) {
                    int t = base + i; if (t > TT-1) t = TT-1;
                    sum += xs[g][t] * w[i*3 + k];
                }
            }
            g_enc[(bn*LL + l)*DM + o] = sum;
        }
    }
}

// ============================================================================
// Kernel B: KV split-K partials (blocks 0..383) + Q projection (blocks 384..607)
// ============================================================================
__device__ __forceinline__ void gemm64_body(const float* __restrict__ A,
                                            const float* __restrict__ W,
                                            int M, int Kld, int k0, int k1,
                                            int bm, int bn0, u64t c2[4][2]) {
    __shared__ float As[16][68];
    __shared__ float Ws[16][68];
    int tid = threadIdx.x;
    int lr = tid >> 2;
    int lc = (tid & 3) * 4;
    int ty = tid >> 4, tx = tid & 15;
    for (int kt = k0; kt < k1; kt += 16) {
        __syncthreads();
        int row = bm + lr;
        float4 av = make_float4(0.f,0.f,0.f,0.f);
        if (row < M) av = *(const float4*)(A + (long)row*Kld + kt + lc);
        As[lc+0][lr] = av.x; As[lc+1][lr] = av.y; As[lc+2][lr] = av.z; As[lc+3][lr] = av.w;
        float4 wv = *(const float4*)(W + (long)(bn0 + lr)*Kld + kt + lc);
        Ws[lc+0][lr] = wv.x; Ws[lc+1][lr] = wv.y; Ws[lc+2][lr] = wv.z; Ws[lc+3][lr] = wv.w;
        __syncthreads();
#pragma unroll
        for (int k = 0; k < 16; ++k) {
            float4 a4 = *(const float4*)&As[k][ty*4];
            ulonglong2 b2 = *(const ulonglong2*)&Ws[k][tx*4];
            u64t a0 = f2pack(a4.x, a4.x), a1 = f2pack(a4.y, a4.y);
            u64t a2 = f2pack(a4.z, a4.z), a3 = f2pack(a4.w, a4.w);
            c2[0][0] = f2fma(a0, b2.x, c2[0][0]); c2[0][1] = f2fma(a0, b2.y, c2[0][1]);
            c2[1][0] = f2fma(a1, b2.x, c2[1][0]); c2[1][1] = f2fma(a1, b2.y, c2[1][1]);
            c2[2][0] = f2fma(a2, b2.x, c2[2][0]); c2[2][1] = f2fma(a2, b2.y, c2[2][1]);
            c2[3][0] = f2fma(a3, b2.x, c2[3][0]); c2[3][1] = f2fma(a3, b2.y, c2[3][1]);
        }
    }
}

__global__ void __launch_bounds__(256) kB_projs(const float* __restrict__ S,
                                                const float* __restrict__ kW,
                                                const float* __restrict__ vW,
                                                const float* __restrict__ qW,
                                                const float* __restrict__ qb) {
    int blk = blockIdx.x, tid = threadIdx.x;
    int ty = tid >> 4, tx = tid & 15;
    u64t c2[4][2] = {};
    if (blk < 384) {
        int bx = blk & 1, by = (blk >> 1) & 15, z = blk >> 5;
        int which = z & 1, seg = z >> 1;
        const float* W = which ? vW : kW;
        float* P = g_kvp[z];
        int bm = by*64, bn0 = bx*64;
        gemm64_body(S, W, STOK, DLLM, seg*128, seg*128 + 128, bm, bn0, c2);
#pragma unroll
        for (int i = 0; i < 4; ++i) {
            int mrow = bm + ty*4 + i;
            if (mrow >= STOK) continue;
#pragma unroll
            for (int jp = 0; jp < 2; ++jp) {
                int ncol = bn0 + tx*4 + jp*2;
                *(float2*)(P + (long)mrow*DM + ncol) = f2unpack(c2[i][jp]);
            }
        }
    } else {
        int t = blk - 384;
        int bm = (t >> 1)*64, bn0 = (t & 1)*64;
        gemm64_body(g_enc, qW, BNQ*LL, DM, 0, DM, bm, bn0, c2);
#pragma unroll
        for (int i = 0; i < 4; ++i) {
            int mrow = bm + ty*4 + i;
#pragma unroll
            for (int jp = 0; jp < 2; ++jp) {
                int ncol = bn0 + tx*4 + jp*2;
                float2 v = f2unpack(c2[i][jp]);
                v.x += qb[ncol]; v.y += qb[ncol+1];
                *(float2*)(g_Qb + (long)mrow*DM + ncol) = v;
            }
        }
    }
}

// ---------------- KV reduce ---------------------------------------------------
__global__ void kv_reduce(const float* __restrict__ kb, const float* __restrict__ vb) {
    int idx = blockIdx.x * 256 + threadIdx.x;
    if (idx >= STOK*DM) return;
    int which = blockIdx.y;
    int col = idx & (DM-1);
    float s = which ? vb[col] : kb[col];
#pragma unroll
    for (int seg = 0; seg < KSEG; ++seg) s += g_kvp[seg*2 + which][idx];
    (which ? g_Vb : g_Kb)[idx] = s;
}

// ============================================================================
// Attention v5: reg-capped (85) for 6 blocks/SM and a single 896-block wave.
// K/V staged through one reused temp each; branch-free, no-max.
// grid (BNQ*2, SPLITS), 128 threads. Thread owns (h, q0, q0+16).
// ============================================================================
__global__ void __launch_bounds__(128, 6) k_attn5() {
    __shared__ ulonglong2 Ks[TS2*32];
    __shared__ ulonglong2 Vs[TS2*32];
    int blk = blockIdx.x, part = blockIdx.y;
    int bn = blk >> 1;
    int tid = threadIdx.x;
    int q0 = ((blk & 1) << 5) + (tid & 15);
    int h  = tid >> 4;
    int s0 = part * (STOK/SPLITS);

    const u64t sc2 = f2pack(0.25f*LOG2E, 0.25f*LOG2E);
    const ulonglong2* Qp0 = (const ulonglong2*)(g_Qb + ((bn*LL + q0)*DM + h*16));
    const ulonglong2* Qp1 = (const ulonglong2*)(g_Qb + ((bn*LL + q0 + 16)*DM + h*16));
    ulonglong2 pa = Qp0[0], pb = Qp0[1], pc = Qp0[2], pd = Qp0[3];
    ulonglong2 ra = Qp1[0], rb = Qp1[1], rc = Qp1[2], rd = Qp1[3];
    pa.x=f2mul(pa.x,sc2); pa.y=f2mul(pa.y,sc2); pb.x=f2mul(pb.x,sc2); pb.y=f2mul(pb.y,sc2);
    pc.x=f2mul(pc.x,sc2); pc.y=f2mul(pc.y,sc2); pd.x=f2mul(pd.x,sc2); pd.y=f2mul(pd.y,sc2);
    ra.x=f2mul(ra.x,sc2); ra.y=f2mul(ra.y,sc2); rb.x=f2mul(rb.x,sc2); rb.y=f2mul(rb.y,sc2);
    rc.x=f2mul(rc.x,sc2); rc.y=f2mul(rc.y,sc2); rd.x=f2mul(rd.x,sc2); rd.y=f2mul(rd.y,sc2);

    float l0 = 0.f, l1 = 0.f;
    u64t A0[8], A1[8];
#pragma unroll
    for (int e = 0; e < 8; ++e) { A0[e] = 0ull; A1[e] = 0ull; }

    for (int t = 0; t < (STOK/SPLITS)/TS2; ++t) {
        __syncthreads();
        const ulonglong2* ksrc = (const ulonglong2*)(g_Kb + (s0 + t*TS2)*DM);
        const ulonglong2* vsrc = (const ulonglong2*)(g_Vb + (s0 + t*TS2)*DM);
        for (int i = tid; i < TS2*32; i += 128) { Ks[i] = ksrc[i]; Vs[i] = vsrc[i]; }
        __syncthreads();
#pragma unroll 5
        for (int s = 0; s < TS2; ++s) {
            int base = s*32 + h*4;
            // --- K phase: one live K temp, reused ---
            ulonglong2 kk = Ks[base];
            u64t d0 = f2mul(pa.x, kk.x);  u64t d1 = f2mul(ra.x, kk.x);
            d0 = f2fma(pa.y, kk.y, d0);   d1 = f2fma(ra.y, kk.y, d1);
            kk = Ks[base+1];
            d0 = f2fma(pb.x, kk.x, d0);   d1 = f2fma(rb.x, kk.x, d1);
            d0 = f2fma(pb.y, kk.y, d0);   d1 = f2fma(rb.y, kk.y, d1);
            kk = Ks[base+2];
            d0 = f2fma(pc.x, kk.x, d0);   d1 = f2fma(rc.x, kk.x, d1);
            d0 = f2fma(pc.y, kk.y, d0);   d1 = f2fma(rc.y, kk.y, d1);
            kk = Ks[base+3];
            d0 = f2fma(pd.x, kk.x, d0);   d1 = f2fma(rd.x, kk.x, d1);
            d0 = f2fma(pd.y, kk.y, d0);   d1 = f2fma(rd.y, kk.y, d1);
            float2 e0 = f2unpack(d0), e1 = f2unpack(d1);
            float p0 = fexp2(e0.x + e0.y);
            float p1 = fexp2(e1.x + e1.y);
            l0 += p0; l1 += p1;
            u64t pp0 = f2pack(p0, p0), pp1 = f2pack(p1, p1);
            // --- V phase: one live V temp, reused ---
            ulonglong2 vv = Vs[base];
            A0[0]=f2fma(pp0,vv.x,A0[0]); A1[0]=f2fma(pp1,vv.x,A1[0]);
            A0[1]=f2fma(pp0,vv.y,A0[1]); A1[1]=f2fma(pp1,vv.y,A1[1]);
            vv = Vs[base+1];
            A0[2]=f2fma(pp0,vv.x,A0[2]); A1[2]=f2fma(pp1,vv.x,A1[2]);
            A0[3]=f2fma(pp0,vv.y,A0[3]); A1[3]=f2fma(pp1,vv.y,A1[3]);
            vv = Vs[base+2];
            A0[4]=f2fma(pp0,vv.x,A0[4]); A1[4]=f2fma(pp1,vv.x,A1[4]);
            A0[5]=f2fma(pp0,vv.y,A0[5]); A1[5]=f2fma(pp1,vv.y,A1[5]);
            vv = Vs[base+3];
            A0[6]=f2fma(pp0,vv.x,A0[6]); A1[6]=f2fma(pp1,vv.x,A1[6]);
            A0[7]=f2fma(pp0,vv.y,A0[7]); A1[7]=f2fma(pp1,vv.y,A1[7]);
        }
    }
    int pi0 = (bn*LL + q0)*8 + h;
    int pi1 = pi0 + 16*8;
    g_lP[part][pi0] = l0;
    g_lP[part][pi1] = l1;
    float* a0p = g_accP[part] + (long)pi0*16;
    float* a1p = g_accP[part] + (long)pi1*16;
#pragma unroll
    for (int i = 0; i < 8; ++i) {
        *(float2*)(a0p + 2*i) = f2unpack(A0[i]);
        *(float2*)(a1p + 2*i) = f2unpack(A1[i]);
    }
}

// combine SPLITS partial (unnormalized) sums -> g_rep
__global__ void k_merge() {
    int t = blockIdx.x * 256 + threadIdx.x;
    if (t >= BNQ*LL*8) return;
    float l = 0.f;
#pragma unroll
    for (int p = 0; p < SPLITS; ++p) l += g_lP[p][t];
    float inv = 1.f / l;
    float4* rp = (float4*)(g_rep + (long)t*16);
#pragma unroll
    for (int i = 0; i < 4; ++i) {
        float4 s = make_float4(0.f,0.f,0.f,0.f);
#pragma unroll
        for (int p = 0; p < SPLITS; ++p) {
            float4 a = *(const float4*)(g_accP[p] + (long)t*16 + i*4);
            s.x += a.x; s.y += a.y; s.z += a.z; s.w += a.w;
        }
        s.x *= inv; s.y *= inv; s.z *= inv; s.w *= inv;
        rp[i] = s;
    }
}

// ---------------- O-projection GEMM 64x128 tile, 4x8 micro -------------------
__global__ void __launch_bounds__(256) gemm_o(const float* __restrict__ A,
                                              const float* __restrict__ W,
                                              const float* __restrict__ bias,
                                              float* __restrict__ C) {
    __shared__ float As[16][68];
    __shared__ float Ws[16][132];
    int bm = blockIdx.y * 64, bn0 = blockIdx.x * 128;
    int tid = threadIdx.x;
    int lr = tid >> 2;
    int lc = (tid & 3) * 4;
    int wr = tid >> 1;
    int wc = (tid & 1) * 8;
    int ty = tid >> 4, tx = tid & 15;
    u64t c2[4][4] = {};
    for (int kt = 0; kt < DM; kt += 16) {
        __syncthreads();
        float4 av = *(const float4*)(A + (long)(bm + lr)*DM + kt + lc);
        As[lc+0][lr] = av.x; As[lc+1][lr] = av.y; As[lc+2][lr] = av.z; As[lc+3][lr] = av.w;
        float4 w0 = *(const float4*)(W + (long)(bn0 + wr)*DM + kt + wc);
        float4 w1 = *(const float4*)(W + (long)(bn0 + wr)*DM + kt + wc + 4);
        Ws[wc+0][wr] = w0.x; Ws[wc+1][wr] = w0.y; Ws[wc+2][wr] = w0.z; Ws[wc+3][wr] = w0.w;
        Ws[wc+4][wr] = w1.x; Ws[wc+5][wr] = w1.y; Ws[wc+6][wr] = w1.z; Ws[wc+7][wr] = w1.w;
        __syncthreads();
#pragma unroll
        for (int k = 0; k < 16; ++k) {
            float4 a4 = *(const float4*)&As[k][ty*4];
            ulonglong2 bA = *(const ulonglong2*)&Ws[k][tx*8];
            ulonglong2 bB = *(const ulonglong2*)&Ws[k][tx*8 + 4];
            u64t a0 = f2pack(a4.x, a4.x), a1 = f2pack(a4.y, a4.y);
            u64t a2 = f2pack(a4.z, a4.z), a3 = f2pack(a4.w, a4.w);
            c2[0][0] = f2fma(a0, bA.x, c2[0][0]); c2[0][1] = f2fma(a0, bA.y, c2[0][1]);
            c2[0][2] = f2fma(a0, bB.x, c2[0][2]); c2[0][3] = f2fma(a0, bB.y, c2[0][3]);
            c2[1][0] = f2fma(a1, bA.x, c2[1][0]); c2[1][1] = f2fma(a1, bA.y, c2[1][1]);
            c2[1][2] = f2fma(a1, bB.x, c2[1][2]); c2[1][3] = f2fma(a1, bB.y, c2[1][3]);
            c2[2][0] = f2fma(a2, bA.x, c2[2][0]); c2[2][1] = f2fma(a2, bA.y, c2[2][1]);
            c2[2][2] = f2fma(a2, bB.x, c2[2][2]); c2[2][3] = f2fma(a2, bB.y, c2[2][3]);
            c2[3][0] = f2fma(a3, bA.x, c2[3][0]); c2[3][1] = f2fma(a3, bA.y, c2[3][1]);
            c2[3][2] = f2fma(a3, bB.x, c2[3][2]); c2[3][3] = f2fma(a3, bB.y, c2[3][3]);
        }
    }
#pragma unroll
    for (int i = 0; i < 4; ++i) {
        int mrow = bm + ty*4 + i;
        const float* ge = g_gemb + (mrow/(NVV*LL))*DLLM;
#pragma unroll
        for (int jp = 0; jp < 4; ++jp) {
            int ncol = bn0 + tx*8 + jp*2;
            float2 v = f2unpack(c2[i][jp]);
            v.x += bias[ncol]   + ge[ncol];
            v.y += bias[ncol+1] + ge[ncol+1];
            *(float2*)(C + (long)mrow*DLLM + ncol) = v;
        }
    }
}

// ---------------- launch -----------------------------------------------------
extern "C" void kernel_launch(void* const* d_in, const int* in_sizes, int n_in,
                              void* d_out, int out_size) {
    const float* node_input = (const float*)d_in[0];
    const float* gat_W      = (const float*)d_in[1];
    const float* a_src      = (const float*)d_in[2];
    const float* a_dst      = (const float*)d_in[3];
    const float* gat_bias   = (const float*)d_in[4];
    const float* x_enc      = (const float*)d_in[5];
    const float* conv_W     = (const float*)d_in[6];
    const float* q_W        = (const float*)d_in[7];
    const float* q_b        = (const float*)d_in[8];
    const float* k_W        = (const float*)d_in[9];
    const float* k_b        = (const float*)d_in[10];
    const float* v_W        = (const float*)d_in[11];
    const float* v_b        = (const float*)d_in[12];
    const float* o_W        = (const float*)d_in[13];
    const float* o_b        = (const float*)d_in[14];
    const float* source_emb = (const float*)d_in[15];
    const int*   edges      = (const int*)d_in[16];
    float* out = (float*)d_out;

    void* pRep;
    cudaGetSymbolAddress(&pRep, g_rep);

    // A: GAT + norm/conv (independent, one launch)
    kA_gat_normconv<<<BB + BNQ/4, 512>>>(node_input, gat_W, a_src, a_dst, gat_bias,
                                         edges, x_enc, conv_W);
    // B: KV split-K partials + Q projection (independent, one launch)
    kB_projs<<<384 + 224, 256>>>(source_emb, k_W, v_W, q_W, q_b);
    // KV reduce (+bias)
    kv_reduce<<<dim3((STOK*DM + 255)/256, 2), 256>>>(k_b, v_b);
    // attention (reg-capped, branch-free, no-max, NQ=2, split-S=4) + merge
    k_attn5<<<dim3(BNQ*2, SPLITS), 128>>>();
    k_merge<<<(BNQ*LL*8 + 255)/256, 256>>>();
    // output projection + bias + graph_emb, writes d_out
    gemm_o<<<dim3(DLLM/128, (BNQ*LL)/64), 256>>>((const float*)pRep, o_W, o_b, out);
}